// round 17
// baseline (speedup 1.0000x reference)
#include <cuda_runtime.h>
#include <cuda_bf16.h>
#include <cstdint>
#include <cstddef>

#define NPIX 200

// ---- gmem scratch (static; zero-initialized at load) -------------------------
__device__ __align__(16) uint8_t g_wh[3u*4*16*10240];          //  2 MB
__device__ __align__(16) uint8_t g_wl[3u*4*16*10240];
__device__ __align__(16) uint8_t g_finh[3u*128*16*17920];      // 110 MB
__device__ __align__(16) uint8_t g_finl[3u*128*16*17920];
__device__ __align__(16) uint8_t g_fouth[3u*128*16*20480];     // 126 MB (class-major rows)
__device__ __align__(16) uint8_t g_foutl[3u*128*16*20480];
__device__ float g_gram[3u*128*10400];                         //  16 MB, pre-leaky-scaled
__device__ float g_corrpart[3*128*600];
__device__ float g_catpart[48*128*600];

#define CSTAGE 37120
#define C_CTRL 111360
#define CONV_SMEM (C_CTRL + 24)
#define GSTAGE 49152
#define G_CTRL (2*GSTAGE)
#define GRAM_SMEM (G_CTRL + 16)
#define HEADS_SMEM ((10400 + 3969) * 4)   // corr branch is the max

__device__ __forceinline__ uint32_t smem_u32(const void* p) {
    uint32_t r;
    asm("{ .reg .u64 t; cvta.to.shared.u64 t, %1; cvt.u32.u64 %0, t; }" : "=r"(r) : "l"(p));
    return r;
}
#define MBAR_INIT(a, c) asm volatile("mbarrier.init.shared.b64 [%0], %1;" :: "r"(a), "r"(c) : "memory")
#define MBAR_EXPECT(a, n) asm volatile("mbarrier.arrive.expect_tx.shared.b64 _, [%0], %1;" :: "r"(a), "r"(n) : "memory")
#define MBAR_WAIT(a, ph) \
    asm volatile("{\n\t.reg .pred P;\n\tW_%=:\n\t" \
                 "mbarrier.try_wait.parity.acquire.cta.shared::cta.b64 P, [%0], %1, 0x989680;\n\t" \
                 "@!P bra W_%=;\n\t}" :: "r"(a), "r"(ph) : "memory")
#define BULK_G2S(dst, src, bytes, mbar) \
    asm volatile("cp.async.bulk.shared::cluster.global.mbarrier::complete_tx::bytes [%0], [%1], %2, [%3];" \
                 :: "r"(dst), "l"(src), "r"(bytes), "r"(mbar) : "memory")

__device__ __forceinline__ void ldsm4(uint32_t* r, uint32_t a) {
    asm volatile("ldmatrix.sync.aligned.m8n8.x4.shared.b16 {%0,%1,%2,%3}, [%4];"
        : "=r"(r[0]), "=r"(r[1]), "=r"(r[2]), "=r"(r[3]) : "r"(a));
}
__device__ __forceinline__ void ldsm2(uint32_t* r, uint32_t a) {
    asm volatile("ldmatrix.sync.aligned.m8n8.x2.shared.b16 {%0,%1}, [%2];"
        : "=r"(r[0]), "=r"(r[1]) : "r"(a));
}
__device__ __forceinline__ void mma16816(float* c, const uint32_t* a, const uint32_t* b) {
    asm volatile("mma.sync.aligned.m16n8k16.row.col.f32.bf16.bf16.f32 "
        "{%0,%1,%2,%3}, {%4,%5,%6,%7}, {%8,%9}, {%0,%1,%2,%3};"
        : "+f"(c[0]), "+f"(c[1]), "+f"(c[2]), "+f"(c[3])
        : "r"(a[0]), "r"(a[1]), "r"(a[2]), "r"(a[3]), "r"(b[0]), "r"(b[1]));
}
__device__ __forceinline__ void pack8(const float* v, uint4& h, uint4& l) {
    __align__(16) __nv_bfloat16 hb[8], lb[8];
#pragma unroll
    for (int u = 0; u < 8; u++) {
        hb[u] = __float2bfloat16_rn(v[u]);
        lb[u] = __float2bfloat16_rn(v[u] - __bfloat162float(hb[u]));
    }
    h = *reinterpret_cast<uint4*>(hb);
    l = *reinterpret_cast<uint4*>(lb);
}
__device__ __forceinline__ float2 bf2f(uint32_t u) {
    __nv_bfloat162 h = *reinterpret_cast<__nv_bfloat162*>(&u);
    return __bfloat1622float2(h);
}
__device__ __forceinline__ int perm_px(int p) {
    int y = p / 20, x = p - y * 20;
    return ((y & 1) * 2 + (x & 1)) * 50 + (y >> 1) * 10 + (x >> 1);
}
__device__ __forceinline__ float leakyscale(float g) {
    float s = g * (1.f / 512.f);
    return s > 0.f ? s : 0.1f * s;
}

// ---- feats [b][c][p] -> transposed slab layout (z-split); weights on z==0 ----
__global__ __launch_bounds__(256) void convert_feat_kernel(
    const float* __restrict__ f1, const float* __restrict__ f2, const float* __restrict__ f3,
    uint8_t* __restrict__ oh, uint8_t* __restrict__ ol,
    const float* __restrict__ Wa, const float* __restrict__ Wb, const float* __restrict__ Wc,
    uint8_t* __restrict__ owh, uint8_t* __restrict__ owl)
{
    __shared__ float s[32 * 201];
    const int b = blockIdx.x, t = blockIdx.y, zc = blockIdx.z, tid = threadIdx.x;

    if (zc == 0) {
        int idx = (t * 128 + b) * 256 + tid;
        int tt = idx / 32768, rr = idx - tt * 32768;
        int m = rr >> 6, g8 = rr & 63;
        const float* W = (tt == 0) ? Wa : ((tt == 1) ? Wb : Wc);
        float v[8];
#pragma unroll
        for (int u = 0; u < 8; u++) v[u] = W[m * 512 + g8 * 8 + u];
        uint4 vh, vl; pack8(v, vh, vl);
        int mt = m >> 7, mr = m & 127, slab = g8 >> 2, c8 = g8 & 3;
        size_t off = ((size_t)(tt * 4 + mt) * 16 + slab) * 10240 + mr * 80 + c8 * 16;
        *(uint4*)(owh + off) = vh;
        *(uint4*)(owl + off) = vl;
    }

    const float* F = ((t == 0) ? f1 : ((t == 1) ? f2 : f3)) + (size_t)b * 102400;
    uint8_t* obh = oh + ((size_t)t * 128 + b) * 286720;
    uint8_t* obl = ol + ((size_t)t * 128 + b) * 286720;
    for (int c = zc * 4; c < zc * 4 + 4; c++) {
        __syncthreads();
        for (int e = tid; e < 32 * 200; e += 256) {
            int kk = e / 200, n = e - kk * 200;
            s[kk * 201 + n] = F[(size_t)(c * 32 + kk) * 200 + n];
        }
        __syncthreads();
        for (int i = tid; i < 800; i += 256) {
            int p = i >> 2, g8 = i & 3;
            float v[8];
#pragma unroll
            for (int u = 0; u < 8; u++) v[u] = s[(g8 * 8 + u) * 201 + p];
            uint4 vh, vl; pack8(v, vh, vl);
            size_t off = (size_t)c * 17920 + p * 80 + g8 * 16;
            *(uint4*)(obh + off) = vh;
            *(uint4*)(obl + off) = vl;
        }
    }
}

// ---- conv1x1 GEMM: paired-ldsm4 B loads (row-clamped), 8 warps, 3 stages -----
__global__ __launch_bounds__(256, 2) void gemm_conv_kernel(
    const uint8_t* __restrict__ Ah, const uint8_t* __restrict__ Al,
    const uint8_t* __restrict__ Bh, const uint8_t* __restrict__ Bl,
    const float* __restrict__ b0, const float* __restrict__ b1, const float* __restrict__ b2,
    uint8_t* __restrict__ Oh, uint8_t* __restrict__ Ol)
{
    extern __shared__ __align__(128) uint8_t smem[];
    const int tid = threadIdx.x;
    const int mt = blockIdx.x >> 1, nt = blockIdx.x & 1;
    const int b = blockIdx.y, z = blockIdx.z;
    const uint32_t sb = smem_u32(smem);
    const int warp = tid >> 5, lane = tid & 31;
    const int warpM = warp & 3, warpN = warp >> 2;
    const int nvalid = nt ? 96 : 104;
    const uint32_t bBytes = nvalid * 80;
    const uint32_t TXB = 20480 + 2 * bBytes;

    const uint32_t CTRL = sb + C_CTRL;
    if (tid == 0) {
#pragma unroll
        for (int p = 0; p < 3; p++) MBAR_INIT(CTRL + p * 8, 1);
    }
    __syncthreads();

    const uint8_t* pAh = Ah + (size_t)(z * 4 + mt) * 163840;
    const uint8_t* pAl = Al + (size_t)(z * 4 + mt) * 163840;
    const uint8_t* pBh = Bh + (size_t)(z * 128 + b) * 286720 + (size_t)nt * 8320;
    const uint8_t* pBl = Bl + (size_t)(z * 128 + b) * 286720 + (size_t)nt * 8320;

    if (tid == 0) {
#pragma unroll
        for (int s = 0; s < 3; s++) {
            const uint32_t st = sb + s * CSTAGE;
            MBAR_EXPECT(CTRL + s * 8, TXB);
            BULK_G2S(st,         pAh + (size_t)s * 10240, 10240, CTRL + s * 8);
            BULK_G2S(st + 10240, pAl + (size_t)s * 10240, 10240, CTRL + s * 8);
            BULK_G2S(st + 20480,          pBh + (size_t)s * 17920, bBytes, CTRL + s * 8);
            BULK_G2S(st + 20480 + bBytes, pBl + (size_t)s * 17920, bBytes, CTRL + s * 8);
        }
    }

    float c[2][7][4];
#pragma unroll
    for (int i = 0; i < 2; i++)
#pragma unroll
        for (int j = 0; j < 7; j++)
#pragma unroll
            for (int k = 0; k < 4; k++) c[i][j][k] = 0.f;

    const int rB4 = warpN * 56 + (lane & 7) + ((lane >> 4) & 1) * 8;
    const int rB2 = warpN * 56 + (lane & 7) + 48;
    const uint32_t colOff = (uint32_t)(lane & 8) * 2;

    int phF[3] = {0, 0, 0};
    int p = 0;
    for (int s = 0; s < 16; s++) {
        const uint32_t st = sb + p * CSTAGE;
        MBAR_WAIT(CTRL + p * 8, phF[p]); phF[p] ^= 1;

        const uint32_t aBase = st + (warpM * 32 + (lane & 15)) * 80 + (lane & 16);
#pragma unroll
        for (int ks = 0; ks < 2; ks++) {
            const uint32_t kb = ks * 32;
            uint32_t afh[2][4], afl[2][4];
#pragma unroll
            for (int mi = 0; mi < 2; mi++) {
                ldsm4(afh[mi], aBase + mi * 1280 + kb);
                ldsm4(afl[mi], aBase + 10240 + mi * 1280 + kb);
            }
#pragma unroll
            for (int np = 0; np < 4; np++) {
                uint32_t bh[4], bl[4];
                if (np < 3) {
                    int r = rB4 + np * 16;
                    if (r >= nvalid) r = lane & 7;
                    const uint32_t ad = st + 20480 + (uint32_t)r * 80 + colOff + kb;
                    ldsm4(bh, ad);
                    ldsm4(bl, ad + bBytes);
                } else {
                    int r = rB2;
                    if (r >= nvalid) r = lane & 7;
                    const uint32_t ad = st + 20480 + (uint32_t)r * 80 + colOff + kb;
                    ldsm2(bh, ad);
                    ldsm2(bl, ad + bBytes);
                }
#pragma unroll
                for (int u = 0; u < 2; u++) {
                    const int ni = 2 * np + u;
                    if (ni >= 7) break;
                    if (warpN * 56 + ni * 8 >= nvalid) continue;
#pragma unroll
                    for (int mi = 0; mi < 2; mi++) {
                        mma16816(c[mi][ni], afh[mi], &bh[2 * u]);
                        mma16816(c[mi][ni], afh[mi], &bl[2 * u]);
                        mma16816(c[mi][ni], afl[mi], &bh[2 * u]);
                    }
                }
            }
        }
        __syncthreads();
        if (tid == 0 && s + 3 < 16) {
            const int sn = s + 3;
            MBAR_EXPECT(CTRL + p * 8, TXB);
            BULK_G2S(st,         pAh + (size_t)sn * 10240, 10240, CTRL + p * 8);
            BULK_G2S(st + 10240, pAl + (size_t)sn * 10240, 10240, CTRL + p * 8);
            BULK_G2S(st + 20480,          pBh + (size_t)sn * 17920, bBytes, CTRL + p * 8);
            BULK_G2S(st + 20480 + bBytes, pBl + (size_t)sn * 17920, bBytes, CTRL + p * 8);
        }
        p = (p == 2) ? 0 : p + 1;
    }
    __syncthreads();

    const float* bias = (z == 0) ? b0 : ((z == 1) ? b1 : b2);
    __nv_bfloat16* sH = reinterpret_cast<__nv_bfloat16*>(smem);   // [pp<104][m128]
    __nv_bfloat16* sL = sH + 13312;
#pragma unroll
    for (int mi = 0; mi < 2; mi++) {
        const int m0 = warpM * 32 + mi * 16 + (lane >> 2);
        const float bv0 = __ldg(bias + mt * 128 + m0);
        const float bv1 = __ldg(bias + mt * 128 + m0 + 8);
#pragma unroll
        for (int ni = 0; ni < 7; ni++) {
            const int p0 = warpN * 56 + ni * 8 + (lane & 3) * 2;
            if (p0 >= nvalid) continue;
            float v[4] = {c[mi][ni][0] + bv0, c[mi][ni][1] + bv0,
                          c[mi][ni][2] + bv1, c[mi][ni][3] + bv1};
#pragma unroll
            for (int q = 0; q < 4; q++) {
                const int pp = p0 + (q & 1), mm = m0 + (q < 2 ? 0 : 8);
                __nv_bfloat16 h = __float2bfloat16_rn(v[q]);
                sH[pp * 128 + mm] = h;
                sL[pp * 128 + mm] = __float2bfloat16_rn(v[q] - __bfloat162float(h));
            }
        }
    }
    __syncthreads();
    uint8_t* ohB = Oh + ((size_t)(z * 128 + b) * 16 + mt * 4) * 20480;
    uint8_t* olB = Ol + ((size_t)(z * 128 + b) * 16 + mt * 4) * 20480;
    const int tot = nvalid * 16;
    for (int g = tid; g < tot; g += 256) {
        int pp = g >> 4, o = g & 15, q = o >> 2, oo = o & 3;
        int pr = perm_px(nt * 104 + pp);
        uint32_t so = (pp * 128 + q * 32 + oo * 8) * 2;
        size_t dof = (size_t)q * 20480 + pr * 80 + oo * 16;
        *(uint4*)(ohB + dof) = *(uint4*)((uint8_t*)sH + so);
        *(uint4*)(olB + dof) = *(uint4*)((uint8_t*)sL + so);
    }
}

// ---- Gram GEMM: 256-thr CTAs (2/SM); epilogue pre-applies leaky(g/512) -------
__global__ __launch_bounds__(256, 2) void gemm_gram_kernel(
    const uint8_t* __restrict__ Fh, const uint8_t* __restrict__ Fl, float* __restrict__ G)
{
    extern __shared__ __align__(128) uint8_t smem[];
    const int tid = threadIdx.x;
    const int ct = blockIdx.x & 1, zh = blockIdx.x >> 1, b = blockIdx.y;
    const uint32_t sb = smem_u32(smem);
    const int warp = tid >> 5, lane = tid & 31;
    const bool active = (warp < 6);
    const int u = zh * 6 + warp;
    const int pr = u >> 2, rem = u & 3;
    const int cls = rem >> 1, wm = rem & 1;
    const int pa = (pr == 2) ? 1 : 0, pb = (pr == 0) ? 1 : 2;

    const uint32_t CTRL = sb + G_CTRL;
    if (tid == 0) { MBAR_INIT(CTRL, 1); MBAR_INIT(CTRL + 8, 1); }
    __syncthreads();

    size_t baseT[3];
#pragma unroll
    for (int t = 0; t < 3; t++)
        baseT[t] = ((size_t)t * 128 + b) * 327680 + (size_t)ct * 8000;

    if (tid == 0) {
#pragma unroll
        for (int s = 0; s < 2; s++) {
            const uint32_t st = sb + s * GSTAGE;
            MBAR_EXPECT(CTRL + s * 8, 48000);
#pragma unroll
            for (int t = 0; t < 3; t++) {
                BULK_G2S(st + t * 16000,        Fh + baseT[t] + (size_t)s * 20480, 8000, CTRL + s * 8);
                BULK_G2S(st + t * 16000 + 8000, Fl + baseT[t] + (size_t)s * 20480, 8000, CTRL + s * 8);
            }
        }
    }

    float c[2][7][4];
#pragma unroll
    for (int i = 0; i < 2; i++)
#pragma unroll
        for (int j = 0; j < 7; j++)
#pragma unroll
            for (int k = 0; k < 4; k++) c[i][j][k] = 0.f;

    const int rB4 = cls * 50 + (lane & 7) + ((lane >> 4) & 1) * 8;
    const int rB2 = cls * 50 + (lane & 7) + 48;
    const uint32_t colOff = (uint32_t)(lane & 8) * 2;

    int phF[2] = {0, 0};
    for (int s = 0; s < 16; s++) {
        const int p = s & 1;
        const uint32_t st = sb + p * GSTAGE;
        MBAR_WAIT(CTRL + p * 8, phF[p]); phF[p] ^= 1;

        if (active) {
            const uint32_t aBase = st + pa * 16000 + (cls * 50 + wm * 32 + (lane & 15)) * 80 + (lane & 16);
            const uint32_t bBase = st + pb * 16000;
#pragma unroll
            for (int ks = 0; ks < 2; ks++) {
                const uint32_t kb = ks * 32;
                uint32_t afh[2][4], afl[2][4];
#pragma unroll
                for (int mi = 0; mi < 2; mi++) {
                    ldsm4(afh[mi], aBase + mi * 1280 + kb);
                    ldsm4(afl[mi], aBase + 8000 + mi * 1280 + kb);
                }
#pragma unroll
                for (int np = 0; np < 4; np++) {
                    uint32_t bh[4], bl[4];
                    if (np < 3) {
                        const uint32_t ad = bBase + (uint32_t)(rB4 + np * 16) * 80 + colOff + kb;
                        ldsm4(bh, ad);
                        ldsm4(bl, ad + 8000);
                    } else {
                        const uint32_t ad = bBase + (uint32_t)rB2 * 80 + colOff + kb;
                        ldsm2(bh, ad);
                        ldsm2(bl, ad + 8000);
                    }
#pragma unroll
                    for (int v = 0; v < 2; v++) {
                        const int ni = 2 * np + v;
                        if (ni >= 7) break;
#pragma unroll
                        for (int mi = 0; mi < 2; mi++) {
                            mma16816(c[mi][ni], afh[mi], &bh[2 * v]);
                            mma16816(c[mi][ni], afh[mi], &bl[2 * v]);
                            mma16816(c[mi][ni], afl[mi], &bh[2 * v]);
                        }
                    }
                }
            }
        }
        __syncthreads();
        if (tid == 0 && s + 2 < 16) {
            const int sn = s + 2;
            MBAR_EXPECT(CTRL + p * 8, 48000);
#pragma unroll
            for (int t = 0; t < 3; t++) {
                BULK_G2S(st + t * 16000,        Fh + baseT[t] + (size_t)sn * 20480, 8000, CTRL + p * 8);
                BULK_G2S(st + t * 16000 + 8000, Fl + baseT[t] + (size_t)sn * 20480, 8000, CTRL + p * 8);
            }
        }
    }

    if (active) {
        float* Gb = G + ((size_t)pr * 128 + b) * 10400 + (ct * 2 + cls) * 2600;
#pragma unroll
        for (int mi = 0; mi < 2; mi++) {
            const int m = wm * 32 + mi * 16 + (lane >> 2);
#pragma unroll
            for (int ni = 0; ni < 7; ni++) {
                const int n0 = ni * 8 + (lane & 3) * 2;
                if (n0 >= 50) continue;
                if (m < 50)
                    *(float2*)(Gb + m * 52 + n0) =
                        make_float2(leakyscale(c[mi][ni][0]), leakyscale(c[mi][ni][1]));
                if (m + 8 < 50)
                    *(float2*)(Gb + (m + 8) * 52 + n0) =
                        make_float2(leakyscale(c[mi][ni][2]), leakyscale(c[mi][ni][3]));
            }
        }
    }
}

// ---- merged heads: y<9 corr (pair,out), y>=9 cat (tensor,slab). Overlapped. --
__global__ __launch_bounds__(256)
void heads_kernel(const float* __restrict__ Gram, const float* __restrict__ Wcorr,
                  float* __restrict__ corrpart,
                  const uint8_t* __restrict__ Fh, const uint8_t* __restrict__ Fl,
                  const float* __restrict__ Wcat, float* __restrict__ catpart)
{
    extern __shared__ float sh[];
    const int b = blockIdx.x, tid = threadIdx.x;
    const int y = tid / 20, x = tid - y * 20;

    if (blockIdx.y < 9) {
        float* sG = sh;            // 10400: [cls4][50][52], pre-leaky-scaled
        float* sW = sh + 10400;    // 3969 transposed: [tap9][d441]
        const int pair = blockIdx.y / 3, o = blockIdx.y - pair * 3;

        const float4* G4 = reinterpret_cast<const float4*>(Gram + ((size_t)pair * 128 + b) * 10400);
        float4* sG4 = reinterpret_cast<float4*>(sG);
        for (int i = tid; i < 2600; i += 256) sG4[i] = G4[i];
        const float* Wsrc = Wcorr + o * 11907 + pair * 3969;
        for (int i = tid; i < 3969; i += 256) {
            int tap = i / 441, d = i - tap * 441;
            sW[i] = Wsrc[d * 9 + tap];
        }
        __syncthreads();

        if (tid < NPIX) {
            float acc = 0.f;
            for (int ky = 0; ky < 3; ky++) {
                for (int kx = 0; kx < 3; kx++) {
                    int sy = y + ky - 1, sx = x + kx - 1;
                    if ((unsigned)sy >= 10u || (unsigned)sx >= 20u) continue;
                    const int qy = sy >> 1, qx = sx >> 1;
                    const int cc = (sy & 1) * 2 + (sx & 1);
                    const float* g = sG + cc * 2600 + (qy * 10 + qx) * 52;
                    const float* w = sW + (ky * 3 + kx) * 441 + (10 - qy) * 21 + (10 - qx);
#pragma unroll
                    for (int iy = 0; iy < 5; iy++) {
#pragma unroll
                        for (int ix = 0; ix < 10; ix++)
                            acc += g[iy * 10 + ix] * w[iy * 21 + ix];
                    }
                }
            }
            corrpart[((size_t)pair * 128 + b) * 600 + o * 200 + tid] = acc;
        }
    } else {
        float* sF = sh;            // 200 x 36
        float* sW = sh + 7200;     // 864
        const int yy = blockIdx.y - 9;
        const int t = yy / 16, ch = yy - t * 16;

        for (int g = tid; g < 800; g += 256) {
            int p = g >> 2, g8 = g & 3;
            int pr = perm_px(p);
            size_t base = (((size_t)t * 128 + b) * 16 + ch) * 20480 + pr * 80 + g8 * 16;
            uint4 vh = *(const uint4*)(Fh + base);
            uint4 vl = *(const uint4*)(Fl + base);
            float* d = &sF[p * 36 + g8 * 8];
            float2 a0 = bf2f(vh.x), c0 = bf2f(vl.x); d[0] = a0.x + c0.x; d[1] = a0.y + c0.y;
            float2 a1 = bf2f(vh.y), c1 = bf2f(vl.y); d[2] = a1.x + c1.x; d[3] = a1.y + c1.y;
            float2 a2 = bf2f(vh.z), c2 = bf2f(vl.z); d[4] = a2.x + c2.x; d[5] = a2.y + c2.y;
            float2 a3 = bf2f(vh.w), c3 = bf2f(vl.w); d[6] = a3.x + c3.x; d[7] = a3.y + c3.y;
        }
        for (int i = tid; i < 864; i += 256) {
            int o = i / 288, r = i - o * 288;
            int tap = r >> 5, cch = r & 31;
            sW[i] = Wcat[(size_t)(o * 1536 + t * 512 + ch * 32 + cch) * 9 + tap];
        }
        __syncthreads();

        if (tid < NPIX) {
            float acc0 = 0.f, acc1 = 0.f, acc2 = 0.f;
            for (int ky = 0; ky < 3; ky++) {
                int sy = y + ky - 1;
                if ((unsigned)sy >= 10u) continue;
                for (int kx = 0; kx < 3; kx++) {
                    int sx = x + kx - 1;
                    if ((unsigned)sx >= 20u) continue;
                    const float4* v4 = reinterpret_cast<const float4*>(sF + (sy * 20 + sx) * 36);
                    int tap = ky * 3 + kx;
                    const float4* w0 = reinterpret_cast<const float4*>(sW + tap * 32);
                    const float4* w1 = reinterpret_cast<const float4*>(sW + 288 + tap * 32);
                    const float4* w2 = reinterpret_cast<const float4*>(sW + 576 + tap * 32);
#pragma unroll
                    for (int c4 = 0; c4 < 8; c4++) {
                        float4 v = v4[c4];
                        float4 a = w0[c4], bq = w1[c4], cq = w2[c4];
                        acc0 += v.x * a.x + v.y * a.y + v.z * a.z + v.w * a.w;
                        acc1 += v.x * bq.x + v.y * bq.y + v.z * bq.z + v.w * bq.w;
                        acc2 += v.x * cq.x + v.y * cq.y + v.z * cq.z + v.w * cq.w;
                    }
                }
            }
            float* cp = catpart + ((size_t)yy * 128 + b) * 600;
            cp[tid] = acc0; cp[200 + tid] = acc1; cp[400 + tid] = acc2;
        }
    }
}

// ---- MLP heads + final linear (folds partials + bias + relu) ------------------
__global__ __launch_bounds__(256)
void mlp_kernel(const float* __restrict__ corrpart, const float* __restrict__ catpart,
                const float* __restrict__ bcorr, const float* __restrict__ bcat,
                const float* __restrict__ cf_w1, const float* __restrict__ cf_b1,
                const float* __restrict__ cf_w2, const float* __restrict__ cf_b2,
                const float* __restrict__ ccf_w1, const float* __restrict__ ccf_b1,
                const float* __restrict__ ccf_w2, const float* __restrict__ ccf_b2,
                const float* __restrict__ Wout, const float* __restrict__ bout,
                float* __restrict__ out)
{
    __shared__ float sx[600];
    __shared__ float h1[256];
    __shared__ float h2[2][128];
    const int b = blockIdx.x, tid = threadIdx.x;

    for (int path = 0; path < 2; path++) {
        const float* w1 = path == 0 ? cf_w1 : ccf_w1;
        const float* b1 = path == 0 ? cf_b1 : ccf_b1;
        const float* w2 = path == 0 ? cf_w2 : ccf_w2;
        const float* b2 = path == 0 ? cf_b2 : ccf_b2;
        __syncthreads();
        if (path == 0) {
            for (int i = tid; i < 600; i += 256) {
                float v = bcorr[i / 200];
#pragma unroll
                for (int pr = 0; pr < 3; pr++)
                    v += corrpart[((size_t)pr * 128 + b) * 600 + i];
                sx[i] = fmaxf(v, 0.f);
            }
        } else {
            for (int i = tid; i < 600; i += 256) {
                float v = bcat[i / 200];
#pragma unroll
                for (int ch = 0; ch < 48; ch++)
                    v += catpart[((size_t)ch * 128 + b) * 600 + i];
                sx[i] = v;
            }
        }
        __syncthreads();
        {
            float s = b1[tid];
            const float4* wr = reinterpret_cast<const float4*>(w1 + (size_t)tid * 600);
#pragma unroll 4
            for (int k = 0; k < 150; k++) {
                float4 w = wr[k];
                s += w.x * sx[4*k] + w.y * sx[4*k+1] + w.z * sx[4*k+2] + w.w * sx[4*k+3];
            }
            h1[tid] = fmaxf(s, 0.f);
        }
        __syncthreads();
        if (tid < 128) {
            float s = b2[tid];
            const float4* wr = reinterpret_cast<const float4*>(w2 + (size_t)tid * 256);
#pragma unroll 4
            for (int k = 0; k < 64; k++) {
                float4 w = wr[k];
                s += w.x * h1[4*k] + w.y * h1[4*k+1] + w.z * h1[4*k+2] + w.w * h1[4*k+3];
            }
            h2[path][tid] = fmaxf(s, 0.f);
        }
    }
    __syncthreads();
    if (tid < 2) {
        float s = bout[tid];
        const float* wr = Wout + tid * 256;
        for (int i = 0; i < 128; i++)
            s += h2[0][i] * wr[i] + h2[1][i] * wr[128 + i];
        out[b * 2 + tid] = s;
    }
}

// ---- launch -------------------------------------------------------------------
extern "C" void kernel_launch(void* const* d_in, const int* in_sizes, int n_in,
                              void* d_out, int out_size)
{
    (void)in_sizes; (void)n_in; (void)out_size;
    const float* feat1 = (const float*)d_in[0];
    const float* feat2 = (const float*)d_in[1];
    const float* feat3 = (const float*)d_in[2];
    const float* Wa = (const float*)d_in[3];   const float* ba = (const float*)d_in[4];
    const float* Wb = (const float*)d_in[5];   const float* bb = (const float*)d_in[6];
    const float* Wc = (const float*)d_in[7];   const float* bc = (const float*)d_in[8];
    const float* Wcorr = (const float*)d_in[9];  const float* bcorr = (const float*)d_in[10];
    const float* Wcat = (const float*)d_in[11];  const float* bcat = (const float*)d_in[12];
    const float* cf_w1 = (const float*)d_in[13]; const float* cf_b1 = (const float*)d_in[14];
    const float* cf_w2 = (const float*)d_in[15]; const float* cf_b2 = (const float*)d_in[16];
    const float* ccf_w1 = (const float*)d_in[17]; const float* ccf_b1 = (const float*)d_in[18];
    const float* ccf_w2 = (const float*)d_in[19]; const float* ccf_b2 = (const float*)d_in[20];
    const float* Wout = (const float*)d_in[21];  const float* bout = (const float*)d_in[22];

    uint8_t *wh, *wl, *fih, *fil, *foh, *fol;
    float *G, *cvp, *tvp;
    cudaGetSymbolAddress((void**)&wh,  g_wh);
    cudaGetSymbolAddress((void**)&wl,  g_wl);
    cudaGetSymbolAddress((void**)&fih, g_finh);
    cudaGetSymbolAddress((void**)&fil, g_finl);
    cudaGetSymbolAddress((void**)&foh, g_fouth);
    cudaGetSymbolAddress((void**)&fol, g_foutl);
    cudaGetSymbolAddress((void**)&G,   g_gram);
    cudaGetSymbolAddress((void**)&cvp, g_corrpart);
    cudaGetSymbolAddress((void**)&tvp, g_catpart);

    cudaFuncSetAttribute(gemm_conv_kernel, cudaFuncAttributeMaxDynamicSharedMemorySize, CONV_SMEM);
    cudaFuncSetAttribute(gemm_gram_kernel, cudaFuncAttributeMaxDynamicSharedMemorySize, GRAM_SMEM);
    cudaFuncSetAttribute(heads_kernel, cudaFuncAttributeMaxDynamicSharedMemorySize, HEADS_SMEM);

    convert_feat_kernel<<<dim3(128, 3, 4), 256>>>(feat1, feat2, feat3, fih, fil,
                                                  Wa, Wb, Wc, wh, wl);

    gemm_conv_kernel<<<dim3(8, 128, 3), 256, CONV_SMEM>>>(
        wh, wl, fih, fil, ba, bb, bc, foh, fol);

    gemm_gram_kernel<<<dim3(4, 128), 256, GRAM_SMEM>>>(foh, fol, G);

    heads_kernel<<<dim3(128, 57), 256, HEADS_SMEM>>>(G, Wcorr, cvp, foh, fol, Wcat, tvp);

    mlp_kernel<<<128, 256>>>(cvp, tvp, bcorr, bcat,
                             cf_w1, cf_b1, cf_w2, cf_b2,
                             ccf_w1, ccf_b1, ccf_w2, ccf_b2, Wout, bout, (float*)d_out);
}